// round 13
// baseline (speedup 1.0000x reference)
#include <cuda_runtime.h>
#include <cuda_bf16.h>
#include <cstdint>

// Problem constants
// B=64, T=512, V=256, E=512, H=1024, L=4 (only layer 3 matters), D=512
#define BB 64
#define TT 512
#define VV 256
#define EE 512
#define HH 1024
#define DD 512

typedef unsigned long long u64;

// ---------------- scratch (device globals; no allocations allowed) ----------
__device__ float g_hA[HH * BB];                        // hidden, transposed [j][b]
__device__ float g_hB[HH * BB];                        // ping-pong buffer
__device__ float g_gitok[VV * 3 * HH];                 // per-token input-gate table (3MB)
__device__ float g_tops[(size_t)TT * BB * HH];         // top-layer hidden per step (134MB)
__device__ float g_hdec[(size_t)TT * BB * DD];         // decoder hidden (67MB)

// ---------------- f32x2 helpers ---------------------------------------------
__device__ __forceinline__ void fma2(u64& d, u64 a, u64 b) {
    asm("fma.rn.f32x2 %0, %1, %2, %0;" : "+l"(d) : "l"(a), "l"(b));
}
__device__ __forceinline__ void upk(u64 v, float& lo, float& hi) {
    asm("mov.b64 {%0, %1}, %2;" : "=f"(lo), "=f"(hi) : "l"(v));
}

// ---------------- init hidden: hT[j][b] = h0[3][j] ---------------------------
__global__ void init_h_kernel(const float* __restrict__ h03) {
    int idx = blockIdx.x * 256 + threadIdx.x;   // 65536 total
    g_hA[idx] = h03[idx >> 6];
}

// ---------------- generic packed-f32x2 GEMM ----------------------------------
// C[M,N] = act(A[M,K] @ B + bias[N])
// MODE 0: B stored N-major rows ([n][k], row stride ldb, column offset bofs); plain store
// MODE 1: B stored K-major ([k][n], row stride ldb); ReLU
// MODE 2: B stored K-major; plain; permuted store row m=(t*64+b) -> out[(b*512+t)*N + n]
// Tiles: CTA 64x64, 256 threads (16x16), thread 4 rows (2 f32x2 pairs) x 4 cols.
#define GEMM_SMEM ((64 * 66 + 64 * 65 * 2) * 4)   // sA[64][66] f32 + sB[64][65] f32x2 = 50176B

template <int MODE>
__global__ void __launch_bounds__(256) gemm_kernel(
    const float* __restrict__ A, const float* __restrict__ B,
    const float* __restrict__ bias, float* __restrict__ C,
    int M, int N, int K, int lda, int ldb, int bofs)
{
    extern __shared__ float smem[];
    float*  sA = smem;                          // [kk][row], row-pad 66
    float2* sB = (float2*)(smem + 64 * 66);     // [col][kk] duplicated, kk-pad 65

    const int tid = threadIdx.x;
    const int tx = tid & 15, ty = tid >> 4;
    const int m0 = blockIdx.y * 64, n0 = blockIdx.x * 64;

    u64 acc[2][4];
#pragma unroll
    for (int p = 0; p < 2; ++p)
#pragma unroll
        for (int q = 0; q < 4; ++q) acc[p][q] = 0ULL;

    for (int kb = 0; kb < K; kb += 64) {
        // stage A tile transposed: sA[kk][row]
#pragma unroll
        for (int i = 0; i < 4; ++i) {
            int idx = tid + i * 256;
            int row = idx >> 4;
            int k4 = (idx & 15) << 2;
            float4 v = *(const float4*)(A + (size_t)(m0 + row) * lda + kb + k4);
            sA[(k4 + 0) * 66 + row] = v.x;
            sA[(k4 + 1) * 66 + row] = v.y;
            sA[(k4 + 2) * 66 + row] = v.z;
            sA[(k4 + 3) * 66 + row] = v.w;
        }
        // stage B tile duplicated: sB[col][kk] = {w,w}
        if (MODE == 0) {
#pragma unroll
            for (int i = 0; i < 4; ++i) {
                int idx = tid + i * 256;
                int n = idx >> 4;
                int k4 = (idx & 15) << 2;
                float4 v = *(const float4*)(B + (size_t)(n0 + n) * ldb + bofs + kb + k4);
                float2* d = sB + n * 65 + k4;
                d[0] = make_float2(v.x, v.x); d[1] = make_float2(v.y, v.y);
                d[2] = make_float2(v.z, v.z); d[3] = make_float2(v.w, v.w);
            }
        } else {
#pragma unroll
            for (int i = 0; i < 4; ++i) {
                int idx = tid + i * 256;
                int kk = idx >> 4;
                int n4 = (idx & 15) << 2;
                float4 v = *(const float4*)(B + (size_t)(kb + kk) * ldb + n0 + n4);
                sB[(n4 + 0) * 65 + kk] = make_float2(v.x, v.x);
                sB[(n4 + 1) * 65 + kk] = make_float2(v.y, v.y);
                sB[(n4 + 2) * 65 + kk] = make_float2(v.z, v.z);
                sB[(n4 + 3) * 65 + kk] = make_float2(v.w, v.w);
            }
        }
        __syncthreads();
#pragma unroll 8
        for (int kk = 0; kk < 64; ++kk) {
            u64 a01 = *(const u64*)(sA + kk * 66 + 4 * ty);
            u64 a23 = *(const u64*)(sA + kk * 66 + 4 * ty + 2);
#pragma unroll
            for (int q = 0; q < 4; ++q) {
                u64 w = *(const u64*)(sB + (tx + 16 * q) * 65 + kk);
                fma2(acc[0][q], a01, w);
                fma2(acc[1][q], a23, w);
            }
        }
        __syncthreads();
    }

    // epilogue
#pragma unroll
    for (int q = 0; q < 4; ++q) {
        int c = n0 + tx + 16 * q;
        float bv = bias[c];
        float v00, v01, v10, v11;
        upk(acc[0][q], v00, v01);
        upk(acc[1][q], v10, v11);
        float vals[4] = {v00 + bv, v01 + bv, v10 + bv, v11 + bv};
#pragma unroll
        for (int p = 0; p < 4; ++p) {
            int m = m0 + 4 * ty + p;
            float v = vals[p];
            if (MODE == 1) v = fmaxf(v, 0.f);
            if (MODE == 2) {
                int t = m >> 6, b = m & 63;
                C[((size_t)(b << 9) + t) * N + c] = v;
            } else {
                C[(size_t)m * N + c] = v;
            }
        }
    }
}

// ---------------- fused GRU step ---------------------------------------------
// Per step: gh6[64, 6144] = hT @ [Wih_h(3 gates) ; Whh(3 gates)] for this CTA's
// 8 j-columns, then gate math + hidden update, fully fused.
// 128 CTAs (8 j-cols each), 256 threads, thread = 4 batch rows x 3 gate-cols.
#define GRU_SMEM (BB * 256 * 4 + 48 * 257 * 8)   // sh_h 64KB + sh_w(dup,pad) 96.4KB

__global__ void __launch_bounds__(256) gru_step_kernel(
    int t, const int* __restrict__ tok,
    const float* __restrict__ Wih, const float* __restrict__ Whh,
    const float* __restrict__ bhh, const float* __restrict__ gitok)
{
    extern __shared__ float smem[];
    float*  sh_h = smem;                        // [kk][b], 256 x 64, flat == global chunk
    float2* sh_w = (float2*)(smem + 256 * 64);  // [c][kk] duplicated, kk-pad 257

    const float* hin  = (t & 1) ? g_hB : g_hA;
    float*       hout = (t & 1) ? g_hA : g_hB;

    const int tid = threadIdx.x;
    const int tx = tid & 15, ty = tid >> 4;
    const int j0 = blockIdx.x * 8;
    const int b0 = ty * 4;

    u64 acc[2][3];
#pragma unroll
    for (int p = 0; p < 2; ++p)
#pragma unroll
        for (int q = 0; q < 3; ++q) acc[p][q] = 0ULL;

    for (int kc = 0; kc < 4; ++kc) {
        // hT chunk is already [k][b] contiguous -> straight float4 copy
        const float4* hs = (const float4*)(hin + kc * 256 * 64);
        float4* hd = (float4*)sh_h;
#pragma unroll
        for (int i = 0; i < 16; ++i) hd[tid + i * 256] = hs[tid + i * 256];

        // weights: 48 rows (6 gate-blocks x 8 j) x 256 k, duplicated into float2
#pragma unroll
        for (int i = 0; i < 12; ++i) {
            int idx = tid + i * 256;
            int c = idx >> 6;
            int k4 = (idx & 63) << 2;
            int gate = c >> 3, jj = c & 7;
            const float* wr = (gate < 3)
                ? (Wih + (size_t)(gate * HH + j0 + jj) * (HH + EE))       // first H cols of W_ih row
                : (Whh + (size_t)((gate - 3) * HH + j0 + jj) * HH);
            float4 v = *(const float4*)(wr + kc * 256 + k4);
            float2* d = sh_w + c * 257 + k4;
            d[0] = make_float2(v.x, v.x); d[1] = make_float2(v.y, v.y);
            d[2] = make_float2(v.z, v.z); d[3] = make_float2(v.w, v.w);
        }
        __syncthreads();

#pragma unroll 8
        for (int kk = 0; kk < 256; ++kk) {
            u64 a01 = *(const u64*)(sh_h + kk * 64 + b0);
            u64 a23 = *(const u64*)(sh_h + kk * 64 + b0 + 2);
#pragma unroll
            for (int q = 0; q < 3; ++q) {
                u64 w = *(const u64*)(sh_w + (tx + 16 * q) * 257 + kk);
                fma2(acc[0][q], a01, w);
                fma2(acc[1][q], a23, w);
            }
        }
        __syncthreads();
    }

    // share accumulators: sacc[b][c] with c = gate*8 + jj (reuse sh_h space)
    float* sacc = sh_h;
#pragma unroll
    for (int q = 0; q < 3; ++q) {
        int c = tx + 16 * q;
        float v0, v1, v2, v3;
        upk(acc[0][q], v0, v1);
        upk(acc[1][q], v2, v3);
        sacc[(b0 + 0) * 48 + c] = v0;
        sacc[(b0 + 1) * 48 + c] = v1;
        sacc[(b0 + 2) * 48 + c] = v2;
        sacc[(b0 + 3) * 48 + c] = v3;
    }
    __syncthreads();

    // gate math: 512 (b, j) outputs, 2 per thread
#pragma unroll
    for (int o = 0; o < 2; ++o) {
        int oi = tid + o * 256;
        int b = oi >> 3, jj = oi & 7;
        int j = j0 + jj;
        int tk = tok[b * TT + t];
        const float* gt = gitok + (size_t)tk * (3 * HH);   // includes b_ih
        float ir  = sacc[b * 48 +      jj] + gt[j];
        float iz  = sacc[b * 48 +  8 + jj] + gt[HH + j];
        float in_ = sacc[b * 48 + 16 + jj] + gt[2 * HH + j];
        float hr  = sacc[b * 48 + 24 + jj] + bhh[j];
        float hz  = sacc[b * 48 + 32 + jj] + bhh[HH + j];
        float hn  = sacc[b * 48 + 40 + jj] + bhh[2 * HH + j];
        float r = 1.f / (1.f + __expf(-(ir + hr)));
        float z = 1.f / (1.f + __expf(-(iz + hz)));
        float n = tanhf(in_ + r * hn);
        float hold = hin[j * 64 + b];
        float hnew = (1.f - z) * n + z * hold;
        hout[j * 64 + b] = hnew;
        g_tops[((size_t)t * BB + b) * HH + j] = hnew;
    }
}

// ---------------- launch -----------------------------------------------------
extern "C" void kernel_launch(void* const* d_in, const int* in_sizes, int n_in,
                              void* d_out, int out_size)
{
    const int*   tok   = (const int*)d_in[0];
    const float* embed = (const float*)d_in[1];
    const float* W_ih  = (const float*)d_in[2];
    const float* W_hh  = (const float*)d_in[3];
    const float* b_ih  = (const float*)d_in[4];
    const float* b_hh  = (const float*)d_in[5];
    const float* h0    = (const float*)d_in[6];
    const float* W1    = (const float*)d_in[7];
    const float* b1    = (const float*)d_in[8];
    const float* W2    = (const float*)d_in[9];
    const float* b2    = (const float*)d_in[10];
    float* out = (float*)d_out;

    // only layer L-1 = 3 influences the output
    const float* Wih3 = W_ih + (size_t)3 * (3 * HH) * (HH + EE);
    const float* Whh3 = W_hh + (size_t)3 * (3 * HH) * HH;
    const float* bih3 = b_ih + 3 * (3 * HH);
    const float* bhh3 = b_hh + 3 * (3 * HH);
    const float* h03  = h0 + 3 * HH;

    cudaFuncSetAttribute(gru_step_kernel, cudaFuncAttributeMaxDynamicSharedMemorySize, GRU_SMEM);
    cudaFuncSetAttribute(gemm_kernel<0>, cudaFuncAttributeMaxDynamicSharedMemorySize, GEMM_SMEM);
    cudaFuncSetAttribute(gemm_kernel<1>, cudaFuncAttributeMaxDynamicSharedMemorySize, GEMM_SMEM);
    cudaFuncSetAttribute(gemm_kernel<2>, cudaFuncAttributeMaxDynamicSharedMemorySize, GEMM_SMEM);

    float *p_gitok, *p_tops, *p_hdec;
    cudaGetSymbolAddress((void**)&p_gitok, g_gitok);
    cudaGetSymbolAddress((void**)&p_tops, g_tops);
    cudaGetSymbolAddress((void**)&p_hdec, g_hdec);

    // h_T init (transposed [j][b])
    init_h_kernel<<<256, 256>>>(h03);

    // per-token input-gate table: gi_tok[v, 3H] = embed[v] @ W_ihE^T + b_ih
    gemm_kernel<0><<<dim3(48, 4), 256, GEMM_SMEM>>>(
        embed, Wih3, bih3, p_gitok, VV, 3 * HH, EE, EE, HH + EE, HH);

    // serial recurrence, layer 3 only
    for (int t = 0; t < TT; ++t)
        gru_step_kernel<<<128, 256, GRU_SMEM>>>(t, tok, Wih3, Whh3, bhh3, p_gitok);

    // decoder: hdec = relu(tops @ W1 + b1); logits = hdec @ W2 + b2 (permuted to [B,T,V])
    gemm_kernel<1><<<dim3(DD / 64, TT * BB / 64), 256, GEMM_SMEM>>>(
        p_tops, W1, b1, p_hdec, TT * BB, DD, HH, HH, DD, 0);
    gemm_kernel<2><<<dim3(VV / 64, TT * BB / 64), 256, GEMM_SMEM>>>(
        p_hdec, W2, b2, out, TT * BB, VV, DD, DD, VV, 0);
}

// round 14
// speedup vs baseline: 1.0007x; 1.0007x over previous
#include <cuda_runtime.h>
#include <cuda_bf16.h>
#include <cstdint>

// Problem constants
// B=64, T=512, V=256, E=512, H=1024, L=4 (only layer 3 matters), D=512
#define BB 64
#define TT 512
#define VV 256
#define EE 512
#define HH 1024
#define DD 512

typedef unsigned long long u64;

// ---------------- scratch (device globals; no allocations allowed) ----------
__device__ float g_hA[HH * BB];                        // hidden, transposed [j][b]
__device__ float g_hB[HH * BB];                        // ping-pong buffer
__device__ float g_gitok[VV * 3 * HH];                 // per-token input-gate table (3MB)
__device__ float g_tops[(size_t)TT * BB * HH];         // top-layer hidden per step (134MB)
__device__ float g_hdec[(size_t)TT * BB * DD];         // decoder hidden (67MB)

// ---------------- f32x2 helpers ---------------------------------------------
__device__ __forceinline__ void fma2(u64& d, u64 a, u64 b) {
    asm("fma.rn.f32x2 %0, %1, %2, %0;" : "+l"(d) : "l"(a), "l"(b));
}
__device__ __forceinline__ void upk(u64 v, float& lo, float& hi) {
    asm("mov.b64 {%0, %1}, %2;" : "=f"(lo), "=f"(hi) : "l"(v));
}

// ---------------- init hidden: hT[j][b] = h0[3][j] ---------------------------
__global__ void init_h_kernel(const float* __restrict__ h03) {
    int idx = blockIdx.x * 256 + threadIdx.x;   // 65536 total
    g_hA[idx] = h03[idx >> 6];
}

// ---------------- generic packed-f32x2 GEMM ----------------------------------
// C[M,N] = act(A[M,K] @ B + bias[N])
// MODE 0: B stored N-major rows ([n][k], row stride ldb, column offset bofs); plain store
// MODE 1: B stored K-major ([k][n], row stride ldb); ReLU
// MODE 2: B stored K-major; plain; permuted store row m=(t*64+b) -> out[(b*512+t)*N + n]
// Tiles: CTA 64x64, 256 threads (16x16), thread 4 rows (2 f32x2 pairs) x 4 cols.
#define GEMM_SMEM ((64 * 66 + 64 * 65 * 2) * 4)   // sA[64][66] f32 + sB[64][65] f32x2 = 50176B

template <int MODE>
__global__ void __launch_bounds__(256) gemm_kernel(
    const float* __restrict__ A, const float* __restrict__ B,
    const float* __restrict__ bias, float* __restrict__ C,
    int M, int N, int K, int lda, int ldb, int bofs)
{
    extern __shared__ float smem[];
    float*  sA = smem;                          // [kk][row], row-pad 66
    float2* sB = (float2*)(smem + 64 * 66);     // [col][kk] duplicated, kk-pad 65

    const int tid = threadIdx.x;
    const int tx = tid & 15, ty = tid >> 4;
    const int m0 = blockIdx.y * 64, n0 = blockIdx.x * 64;

    u64 acc[2][4];
#pragma unroll
    for (int p = 0; p < 2; ++p)
#pragma unroll
        for (int q = 0; q < 4; ++q) acc[p][q] = 0ULL;

    for (int kb = 0; kb < K; kb += 64) {
        // stage A tile transposed: sA[kk][row]
#pragma unroll
        for (int i = 0; i < 4; ++i) {
            int idx = tid + i * 256;
            int row = idx >> 4;
            int k4 = (idx & 15) << 2;
            float4 v = *(const float4*)(A + (size_t)(m0 + row) * lda + kb + k4);
            sA[(k4 + 0) * 66 + row] = v.x;
            sA[(k4 + 1) * 66 + row] = v.y;
            sA[(k4 + 2) * 66 + row] = v.z;
            sA[(k4 + 3) * 66 + row] = v.w;
        }
        // stage B tile duplicated: sB[col][kk] = {w,w}
        if (MODE == 0) {
#pragma unroll
            for (int i = 0; i < 4; ++i) {
                int idx = tid + i * 256;
                int n = idx >> 4;
                int k4 = (idx & 15) << 2;
                float4 v = *(const float4*)(B + (size_t)(n0 + n) * ldb + bofs + kb + k4);
                float2* d = sB + n * 65 + k4;
                d[0] = make_float2(v.x, v.x); d[1] = make_float2(v.y, v.y);
                d[2] = make_float2(v.z, v.z); d[3] = make_float2(v.w, v.w);
            }
        } else {
#pragma unroll
            for (int i = 0; i < 4; ++i) {
                int idx = tid + i * 256;
                int kk = idx >> 4;
                int n4 = (idx & 15) << 2;
                float4 v = *(const float4*)(B + (size_t)(kb + kk) * ldb + n0 + n4);
                sB[(n4 + 0) * 65 + kk] = make_float2(v.x, v.x);
                sB[(n4 + 1) * 65 + kk] = make_float2(v.y, v.y);
                sB[(n4 + 2) * 65 + kk] = make_float2(v.z, v.z);
                sB[(n4 + 3) * 65 + kk] = make_float2(v.w, v.w);
            }
        }
        __syncthreads();
#pragma unroll 8
        for (int kk = 0; kk < 64; ++kk) {
            u64 a01 = *(const u64*)(sA + kk * 66 + 4 * ty);
            u64 a23 = *(const u64*)(sA + kk * 66 + 4 * ty + 2);
#pragma unroll
            for (int q = 0; q < 4; ++q) {
                u64 w = *(const u64*)(sB + (tx + 16 * q) * 65 + kk);
                fma2(acc[0][q], a01, w);
                fma2(acc[1][q], a23, w);
            }
        }
        __syncthreads();
    }

    // epilogue
#pragma unroll
    for (int q = 0; q < 4; ++q) {
        int c = n0 + tx + 16 * q;
        float bv = bias[c];
        float v00, v01, v10, v11;
        upk(acc[0][q], v00, v01);
        upk(acc[1][q], v10, v11);
        float vals[4] = {v00 + bv, v01 + bv, v10 + bv, v11 + bv};
#pragma unroll
        for (int p = 0; p < 4; ++p) {
            int m = m0 + 4 * ty + p;
            float v = vals[p];
            if (MODE == 1) v = fmaxf(v, 0.f);
            if (MODE == 2) {
                int t = m >> 6, b = m & 63;
                C[((size_t)(b << 9) + t) * N + c] = v;
            } else {
                C[(size_t)m * N + c] = v;
            }
        }
    }
}

// ---------------- fused GRU step ---------------------------------------------
// Per step: gh6[64, 6144] = hT @ [Wih_h(3 gates) ; Whh(3 gates)] for this CTA's
// 8 j-columns, then gate math + hidden update, fully fused.
// 128 CTAs (8 j-cols each), 256 threads, thread = 4 batch rows x 3 gate-cols.
#define GRU_SMEM (BB * 256 * 4 + 48 * 257 * 8)   // sh_h 64KB + sh_w(dup,pad) 96.4KB

__global__ void __launch_bounds__(256) gru_step_kernel(
    int t, const int* __restrict__ tok,
    const float* __restrict__ Wih, const float* __restrict__ Whh,
    const float* __restrict__ bhh, const float* __restrict__ gitok)
{
    extern __shared__ float smem[];
    float*  sh_h = smem;                        // [kk][b], 256 x 64, flat == global chunk
    float2* sh_w = (float2*)(smem + 256 * 64);  // [c][kk] duplicated, kk-pad 257

    const float* hin  = (t & 1) ? g_hB : g_hA;
    float*       hout = (t & 1) ? g_hA : g_hB;

    const int tid = threadIdx.x;
    const int tx = tid & 15, ty = tid >> 4;
    const int j0 = blockIdx.x * 8;
    const int b0 = ty * 4;

    u64 acc[2][3];
#pragma unroll
    for (int p = 0; p < 2; ++p)
#pragma unroll
        for (int q = 0; q < 3; ++q) acc[p][q] = 0ULL;

    for (int kc = 0; kc < 4; ++kc) {
        // hT chunk is already [k][b] contiguous -> straight float4 copy
        const float4* hs = (const float4*)(hin + kc * 256 * 64);
        float4* hd = (float4*)sh_h;
#pragma unroll
        for (int i = 0; i < 16; ++i) hd[tid + i * 256] = hs[tid + i * 256];

        // weights: 48 rows (6 gate-blocks x 8 j) x 256 k, duplicated into float2
#pragma unroll
        for (int i = 0; i < 12; ++i) {
            int idx = tid + i * 256;
            int c = idx >> 6;
            int k4 = (idx & 63) << 2;
            int gate = c >> 3, jj = c & 7;
            const float* wr = (gate < 3)
                ? (Wih + (size_t)(gate * HH + j0 + jj) * (HH + EE))       // first H cols of W_ih row
                : (Whh + (size_t)((gate - 3) * HH + j0 + jj) * HH);
            float4 v = *(const float4*)(wr + kc * 256 + k4);
            float2* d = sh_w + c * 257 + k4;
            d[0] = make_float2(v.x, v.x); d[1] = make_float2(v.y, v.y);
            d[2] = make_float2(v.z, v.z); d[3] = make_float2(v.w, v.w);
        }
        __syncthreads();

#pragma unroll 8
        for (int kk = 0; kk < 256; ++kk) {
            u64 a01 = *(const u64*)(sh_h + kk * 64 + b0);
            u64 a23 = *(const u64*)(sh_h + kk * 64 + b0 + 2);
#pragma unroll
            for (int q = 0; q < 3; ++q) {
                u64 w = *(const u64*)(sh_w + (tx + 16 * q) * 257 + kk);
                fma2(acc[0][q], a01, w);
                fma2(acc[1][q], a23, w);
            }
        }
        __syncthreads();
    }

    // share accumulators: sacc[b][c] with c = gate*8 + jj (reuse sh_h space)
    float* sacc = sh_h;
#pragma unroll
    for (int q = 0; q < 3; ++q) {
        int c = tx + 16 * q;
        float v0, v1, v2, v3;
        upk(acc[0][q], v0, v1);
        upk(acc[1][q], v2, v3);
        sacc[(b0 + 0) * 48 + c] = v0;
        sacc[(b0 + 1) * 48 + c] = v1;
        sacc[(b0 + 2) * 48 + c] = v2;
        sacc[(b0 + 3) * 48 + c] = v3;
    }
    __syncthreads();

    // gate math: 512 (b, j) outputs, 2 per thread
#pragma unroll
    for (int o = 0; o < 2; ++o) {
        int oi = tid + o * 256;
        int b = oi >> 3, jj = oi & 7;
        int j = j0 + jj;
        int tk = tok[b * TT + t];
        const float* gt = gitok + (size_t)tk * (3 * HH);   // includes b_ih
        float ir  = sacc[b * 48 +      jj] + gt[j];
        float iz  = sacc[b * 48 +  8 + jj] + gt[HH + j];
        float in_ = sacc[b * 48 + 16 + jj] + gt[2 * HH + j];
        float hr  = sacc[b * 48 + 24 + jj] + bhh[j];
        float hz  = sacc[b * 48 + 32 + jj] + bhh[HH + j];
        float hn  = sacc[b * 48 + 40 + jj] + bhh[2 * HH + j];
        float r = 1.f / (1.f + __expf(-(ir + hr)));
        float z = 1.f / (1.f + __expf(-(iz + hz)));
        float n = tanhf(in_ + r * hn);
        float hold = hin[j * 64 + b];
        float hnew = (1.f - z) * n + z * hold;
        hout[j * 64 + b] = hnew;
        g_tops[((size_t)t * BB + b) * HH + j] = hnew;
    }
}

// ---------------- launch -----------------------------------------------------
extern "C" void kernel_launch(void* const* d_in, const int* in_sizes, int n_in,
                              void* d_out, int out_size)
{
    const int*   tok   = (const int*)d_in[0];
    const float* embed = (const float*)d_in[1];
    const float* W_ih  = (const float*)d_in[2];
    const float* W_hh  = (const float*)d_in[3];
    const float* b_ih  = (const float*)d_in[4];
    const float* b_hh  = (const float*)d_in[5];
    const float* h0    = (const float*)d_in[6];
    const float* W1    = (const float*)d_in[7];
    const float* b1    = (const float*)d_in[8];
    const float* W2    = (const float*)d_in[9];
    const float* b2    = (const float*)d_in[10];
    float* out = (float*)d_out;

    // only layer L-1 = 3 influences the output
    const float* Wih3 = W_ih + (size_t)3 * (3 * HH) * (HH + EE);
    const float* Whh3 = W_hh + (size_t)3 * (3 * HH) * HH;
    const float* bih3 = b_ih + 3 * (3 * HH);
    const float* bhh3 = b_hh + 3 * (3 * HH);
    const float* h03  = h0 + 3 * HH;

    cudaFuncSetAttribute(gru_step_kernel, cudaFuncAttributeMaxDynamicSharedMemorySize, GRU_SMEM);
    cudaFuncSetAttribute(gemm_kernel<0>, cudaFuncAttributeMaxDynamicSharedMemorySize, GEMM_SMEM);
    cudaFuncSetAttribute(gemm_kernel<1>, cudaFuncAttributeMaxDynamicSharedMemorySize, GEMM_SMEM);
    cudaFuncSetAttribute(gemm_kernel<2>, cudaFuncAttributeMaxDynamicSharedMemorySize, GEMM_SMEM);

    float *p_gitok, *p_tops, *p_hdec;
    cudaGetSymbolAddress((void**)&p_gitok, g_gitok);
    cudaGetSymbolAddress((void**)&p_tops, g_tops);
    cudaGetSymbolAddress((void**)&p_hdec, g_hdec);

    // h_T init (transposed [j][b])
    init_h_kernel<<<256, 256>>>(h03);

    // per-token input-gate table: gi_tok[v, 3H] = embed[v] @ W_ihE^T + b_ih
    gemm_kernel<0><<<dim3(48, 4), 256, GEMM_SMEM>>>(
        embed, Wih3, bih3, p_gitok, VV, 3 * HH, EE, EE, HH + EE, HH);

    // serial recurrence, layer 3 only
    for (int t = 0; t < TT; ++t)
        gru_step_kernel<<<128, 256, GRU_SMEM>>>(t, tok, Wih3, Whh3, bhh3, p_gitok);

    // decoder: hdec = relu(tops @ W1 + b1); logits = hdec @ W2 + b2 (permuted to [B,T,V])
    gemm_kernel<1><<<dim3(DD / 64, TT * BB / 64), 256, GEMM_SMEM>>>(
        p_tops, W1, b1, p_hdec, TT * BB, DD, HH, HH, DD, 0);
    gemm_kernel<2><<<dim3(VV / 64, TT * BB / 64), 256, GEMM_SMEM>>>(
        p_hdec, W2, b2, out, TT * BB, VV, DD, DD, VV, 0);
}

// round 17
// speedup vs baseline: 1.0977x; 1.0970x over previous
#include <cuda_runtime.h>
#include <cuda_bf16.h>
#include <cstdint>

// B=64, T=512, V=256, E=512, H=1024, L=4 (only layer 3 matters), D=512
#define BB 64
#define TT 512
#define VV 256
#define EE 512
#define HH 1024
#define DD 512
#define NCTA 128

typedef unsigned long long u64;

// ---------------- scratch (device globals; no allocations allowed) ----------
__device__ u64   g_hdA[BB * HH];                       // hidden, duplicated {v,v}, [b][k]
__device__ u64   g_hdB[BB * HH];                       // ping-pong
__device__ unsigned g_bar;                             // grid barrier counter
__device__ float g_gitok[VV * 3 * HH];                 // per-token input-gate table
__device__ float g_tops[(size_t)TT * BB * HH];         // top-layer hidden per step
__device__ float g_hdec[(size_t)TT * BB * DD];         // decoder hidden

// ---------------- f32x2 helpers ---------------------------------------------
__device__ __forceinline__ void fma2(u64& d, u64 a, u64 b) {
    asm("fma.rn.f32x2 %0, %1, %2, %0;" : "+l"(d) : "l"(a), "l"(b));
}
__device__ __forceinline__ void upk(u64 v, float& lo, float& hi) {
    asm("mov.b64 {%0, %1}, %2;" : "=f"(lo), "=f"(hi) : "l"(v));
}
__device__ __forceinline__ u64 dup2(float v) {
    u64 r;
    asm("mov.b64 %0, {%1, %1};" : "=l"(r) : "f"(v));
    return r;
}

// ---------------- init: h dup buffer + barrier reset -------------------------
__global__ void init_kernel(const float* __restrict__ h03) {
    int idx = blockIdx.x * 256 + threadIdx.x;   // 65536 total
    int b = idx >> 10, k = idx & 1023;
    g_hdA[b * 1024 + k] = dup2(h03[k]);
    if (idx == 0) g_bar = 0;
}

// ---------------- generic packed-f32x2 GEMM (unchanged, passing) -------------
#define GEMM_SMEM ((64 * 66 + 64 * 65 * 2) * 4)

template <int MODE>
__global__ void __launch_bounds__(256) gemm_kernel(
    const float* __restrict__ A, const float* __restrict__ B,
    const float* __restrict__ bias, float* __restrict__ C,
    int M, int N, int K, int lda, int ldb, int bofs)
{
    extern __shared__ float smemf[];
    float*  sA = smemf;
    float2* sB = (float2*)(smemf + 64 * 66);

    const int tid = threadIdx.x;
    const int tx = tid & 15, ty = tid >> 4;
    const int m0 = blockIdx.y * 64, n0 = blockIdx.x * 64;

    u64 acc[2][4];
#pragma unroll
    for (int p = 0; p < 2; ++p)
#pragma unroll
        for (int q = 0; q < 4; ++q) acc[p][q] = 0ULL;

    for (int kb = 0; kb < K; kb += 64) {
#pragma unroll
        for (int i = 0; i < 4; ++i) {
            int idx = tid + i * 256;
            int row = idx >> 4;
            int k4 = (idx & 15) << 2;
            float4 v = *(const float4*)(A + (size_t)(m0 + row) * lda + kb + k4);
            sA[(k4 + 0) * 66 + row] = v.x;
            sA[(k4 + 1) * 66 + row] = v.y;
            sA[(k4 + 2) * 66 + row] = v.z;
            sA[(k4 + 3) * 66 + row] = v.w;
        }
        if (MODE == 0) {
#pragma unroll
            for (int i = 0; i < 4; ++i) {
                int idx = tid + i * 256;
                int n = idx >> 4;
                int k4 = (idx & 15) << 2;
                float4 v = *(const float4*)(B + (size_t)(n0 + n) * ldb + bofs + kb + k4);
                float2* d = sB + n * 65 + k4;
                d[0] = make_float2(v.x, v.x); d[1] = make_float2(v.y, v.y);
                d[2] = make_float2(v.z, v.z); d[3] = make_float2(v.w, v.w);
            }
        } else {
#pragma unroll
            for (int i = 0; i < 4; ++i) {
                int idx = tid + i * 256;
                int kk = idx >> 4;
                int n4 = (idx & 15) << 2;
                float4 v = *(const float4*)(B + (size_t)(kb + kk) * ldb + n0 + n4);
                sB[(n4 + 0) * 65 + kk] = make_float2(v.x, v.x);
                sB[(n4 + 1) * 65 + kk] = make_float2(v.y, v.y);
                sB[(n4 + 2) * 65 + kk] = make_float2(v.z, v.z);
                sB[(n4 + 3) * 65 + kk] = make_float2(v.w, v.w);
            }
        }
        __syncthreads();
#pragma unroll 8
        for (int kk = 0; kk < 64; ++kk) {
            u64 a01 = *(const u64*)(sA + kk * 66 + 4 * ty);
            u64 a23 = *(const u64*)(sA + kk * 66 + 4 * ty + 2);
#pragma unroll
            for (int q = 0; q < 4; ++q) {
                u64 w = *(const u64*)(sB + (tx + 16 * q) * 65 + kk);
                fma2(acc[0][q], a01, w);
                fma2(acc[1][q], a23, w);
            }
        }
        __syncthreads();
    }

#pragma unroll
    for (int q = 0; q < 4; ++q) {
        int c = n0 + tx + 16 * q;
        float bv = bias[c];
        float v00, v01, v10, v11;
        upk(acc[0][q], v00, v01);
        upk(acc[1][q], v10, v11);
        float vals[4] = {v00 + bv, v01 + bv, v10 + bv, v11 + bv};
#pragma unroll
        for (int p = 0; p < 4; ++p) {
            int m = m0 + 4 * ty + p;
            float v = vals[p];
            if (MODE == 1) v = fmaxf(v, 0.f);
            if (MODE == 2) {
                int t = m >> 6, b = m & 63;
                C[((size_t)(b << 9) + t) * N + c] = v;
            } else {
                C[(size_t)m * N + c] = v;
            }
        }
    }
}

// ---------------- persistent GRU recurrence ----------------------------------
// 128 CTAs (one per SM), each owns 8 j-columns of layer 3.
// Weights (48 rows x 1024 k = 192KB) live in SMEM for the whole kernel as
// j-pair float2. Hidden state circulates through global dup buffers {v,v}.
// Per step: fused 64x48x1024 GEMM (f32x2) + gate math + grid barrier.
#define W_STRIDE 1026                                 // u64 per cpair row (pad for banks)
#define SMEM_W_U64 (24 * W_STRIDE)
#define SMEM_H_U64 (64 * 64)
#define GRU_SMEM_B ((SMEM_W_U64 + SMEM_H_U64) * 8)    // 196992 + 32768 = 229760 B

__global__ void __launch_bounds__(256, 1) gru_persist(
    const int* __restrict__ tok,
    const float* __restrict__ Wih, const float* __restrict__ Whh,
    const float* __restrict__ bhh, const float* __restrict__ gitok)
{
    extern __shared__ u64 smem[];
    u64* sw = smem;                    // [24 cpairs][1026]  {w_c_even, w_c_odd}
    u64* sh = smem + SMEM_W_U64;       // [64 b][64 kk] swizzled, dup {h,h}

    const int tid = threadIdx.x;
    const int tu = tid & 7;            // cpairs tu, tu+8, tu+16
    const int tv = tid >> 3;           // 0..31 -> batches 2tv, 2tv+1
    const int j0 = blockIdx.x * 8;

    // ---- stage weights ONCE (c = gate*8 + jj; cpair = c>>1) ----
    {
        float* swf = (float*)sw;
        for (int it = 0; it < 192; ++it) {
            int idx = it * 256 + tid;
            int c = idx >> 10, k = idx & 1023;
            int gate = c >> 3, jj = c & 7;
            const float* wr = (gate < 3)
                ? Wih + (size_t)(gate * HH + j0 + jj) * (HH + EE)
                : Whh + (size_t)((gate - 3) * HH + j0 + jj) * HH;
            swf[((c >> 1) * W_STRIDE + k) * 2 + (c & 1)] = wr[k];
        }
    }

    // per-thread constants
    const int kkl = tid & 63;          // staging column
    const int tb  = tid >> 6;          // staging row base
    const int b0  = 2 * tv;
    const int swzA = (b0 & 7) << 1;    // even; b0+1 uses swzA^2
    u64* hA = sh + b0 * 64;
    u64* hB = sh + (b0 + 1) * 64;
    const u64* wp0 = sw + tu * W_STRIDE;
    const u64* wp1 = wp0 + 8 * W_STRIDE;
    const u64* wp2 = wp0 + 16 * W_STRIDE;

    u64 acc[3][2];
    u64 pf[16];

    for (int t = 0; t < TT; ++t) {
        const u64* hin  = (t & 1) ? g_hdB : g_hdA;
        u64*       hout = (t & 1) ? g_hdA : g_hdB;

#pragma unroll
        for (int i = 0; i < 3; ++i) { acc[i][0] = 0ULL; acc[i][1] = 0ULL; }

        // prefetch chunk 0 (safe: after previous step's grid barrier)
#pragma unroll
        for (int i = 0; i < 16; ++i)
            pf[i] = hin[(size_t)(i * 4 + tb) * 1024 + kkl];

        for (int kc = 0; kc < 16; ++kc) {
            __syncthreads();
#pragma unroll
            for (int i = 0; i < 16; ++i) {
                int b = i * 4 + tb;
                sh[b * 64 + (kkl ^ ((b & 7) << 1))] = pf[i];
            }
            __syncthreads();
            if (kc < 15) {
#pragma unroll
                for (int i = 0; i < 16; ++i)
                    pf[i] = hin[(size_t)(i * 4 + tb) * 1024 + (kc + 1) * 64 + kkl];
            }
            // BUGFIX (R15): weights must advance with the k-chunk
            const u64* w0b = wp0 + kc * 64;
            const u64* w1b = wp1 + kc * 64;
            const u64* w2b = wp2 + kc * 64;
#pragma unroll 8
            for (int kk = 0; kk < 64; kk += 2) {
                int xa = kk ^ swzA;
                ulonglong2 h0 = *(const ulonglong2*)(hA + xa);
                ulonglong2 h1 = *(const ulonglong2*)(hB + (xa ^ 2));
                ulonglong2 w0 = *(const ulonglong2*)(w0b + kk);
                ulonglong2 w1 = *(const ulonglong2*)(w1b + kk);
                ulonglong2 w2 = *(const ulonglong2*)(w2b + kk);
                fma2(acc[0][0], w0.x, h0.x); fma2(acc[0][0], w0.y, h0.y);
                fma2(acc[0][1], w0.x, h1.x); fma2(acc[0][1], w0.y, h1.y);
                fma2(acc[1][0], w1.x, h0.x); fma2(acc[1][0], w1.y, h0.y);
                fma2(acc[1][1], w1.x, h1.x); fma2(acc[1][1], w1.y, h1.y);
                fma2(acc[2][0], w2.x, h0.x); fma2(acc[2][0], w2.y, h0.y);
                fma2(acc[2][1], w2.x, h1.x); fma2(acc[2][1], w2.y, h1.y);
            }
        }

        // exchange accumulators: sacc u64 [b][24 cpairs]  (floats: [b][48], c=gate*8+jj)
        __syncthreads();
        u64* sacc = sh;
        sacc[b0 * 24 + tu]            = acc[0][0];
        sacc[b0 * 24 + tu + 8]        = acc[1][0];
        sacc[b0 * 24 + tu + 16]       = acc[2][0];
        sacc[(b0 + 1) * 24 + tu]      = acc[0][1];
        sacc[(b0 + 1) * 24 + tu + 8]  = acc[1][1];
        sacc[(b0 + 1) * 24 + tu + 16] = acc[2][1];
        __syncthreads();

        // gate math: 512 (b, j) outputs, 2 per thread
        const float* saccf = (const float*)sacc;
#pragma unroll
        for (int o = 0; o < 2; ++o) {
            int oi = tid + o * 256;
            int b = oi >> 3, jj = oi & 7;
            int j = j0 + jj;
            int tk = __ldg(tok + b * TT + t);
            const float* gt = gitok + (size_t)tk * (3 * HH);   // includes b_ih
            float ir  = saccf[b * 48 +      jj] + gt[j];
            float iz  = saccf[b * 48 +  8 + jj] + gt[HH + j];
            float in_ = saccf[b * 48 + 16 + jj] + gt[2 * HH + j];
            float hr  = saccf[b * 48 + 24 + jj] + bhh[j];
            float hz  = saccf[b * 48 + 32 + jj] + bhh[HH + j];
            float hn  = saccf[b * 48 + 40 + jj] + bhh[2 * HH + j];
            float r = 1.f / (1.f + __expf(-(ir + hr)));
            float z = 1.f / (1.f + __expf(-(iz + hz)));
            float n = tanhf(in_ + r * hn);
            float hold = ((const float*)(hin + (size_t)b * 1024 + j))[0];
            float hnew = (1.f - z) * n + z * hold;
            hout[(size_t)b * 1024 + j] = dup2(hnew);
            g_tops[((size_t)t * BB + b) * HH + j] = hnew;
        }

        // grid barrier (all 128 CTAs co-resident; counter reset by init_kernel)
        __syncthreads();
        if (tid == 0) {
            __threadfence();
            atomicAdd(&g_bar, 1u);
            unsigned target = (unsigned)NCTA * (unsigned)(t + 1);
            while (*(volatile unsigned*)&g_bar < target) { }
            __threadfence();
        }
        __syncthreads();
    }
}

// ---------------- launch -----------------------------------------------------
extern "C" void kernel_launch(void* const* d_in, const int* in_sizes, int n_in,
                              void* d_out, int out_size)
{
    const int*   tok   = (const int*)d_in[0];
    const float* embed = (const float*)d_in[1];
    const float* W_ih  = (const float*)d_in[2];
    const float* W_hh  = (const float*)d_in[3];
    const float* b_ih  = (const float*)d_in[4];
    const float* b_hh  = (const float*)d_in[5];
    const float* h0    = (const float*)d_in[6];
    const float* W1    = (const float*)d_in[7];
    const float* b1    = (const float*)d_in[8];
    const float* W2    = (const float*)d_in[9];
    const float* b2    = (const float*)d_in[10];
    float* out = (float*)d_out;

    // only layer L-1 = 3 influences the output
    const float* Wih3 = W_ih + (size_t)3 * (3 * HH) * (HH + EE);
    const float* Whh3 = W_hh + (size_t)3 * (3 * HH) * HH;
    const float* bih3 = b_ih + 3 * (3 * HH);
    const float* bhh3 = b_hh + 3 * (3 * HH);
    const float* h03  = h0 + 3 * HH;

    cudaFuncSetAttribute(gru_persist, cudaFuncAttributeMaxDynamicSharedMemorySize, GRU_SMEM_B);
    cudaFuncSetAttribute(gemm_kernel<0>, cudaFuncAttributeMaxDynamicSharedMemorySize, GEMM_SMEM);
    cudaFuncSetAttribute(gemm_kernel<1>, cudaFuncAttributeMaxDynamicSharedMemorySize, GEMM_SMEM);
    cudaFuncSetAttribute(gemm_kernel<2>, cudaFuncAttributeMaxDynamicSharedMemorySize, GEMM_SMEM);

    float *p_gitok, *p_tops, *p_hdec;
    cudaGetSymbolAddress((void**)&p_gitok, g_gitok);
    cudaGetSymbolAddress((void**)&p_tops, g_tops);
    cudaGetSymbolAddress((void**)&p_hdec, g_hdec);

    // h dup init + barrier reset
    init_kernel<<<256, 256>>>(h03);

    // per-token input-gate table: gi_tok[v, 3H] = embed[v] @ W_ihE^T + b_ih
    gemm_kernel<0><<<dim3(48, 4), 256, GEMM_SMEM>>>(
        embed, Wih3, bih3, p_gitok, VV, 3 * HH, EE, EE, HH + EE, HH);

    // persistent recurrence (all 512 steps in one kernel, weights SMEM-resident)
    gru_persist<<<NCTA, 256, GRU_SMEM_B>>>(tok, Wih3, Whh3, bhh3, p_gitok);

    // decoder: hdec = relu(tops @ W1 + b1); logits = hdec @ W2 + b2 ([B,T,V])
    gemm_kernel<1><<<dim3(DD / 64, TT * BB / 64), 256, GEMM_SMEM>>>(
        p_tops, W1, b1, p_hdec, TT * BB, DD, HH, HH, DD, 0);
    gemm_kernel<2><<<dim3(VV / 64, TT * BB / 64), 256, GEMM_SMEM>>>(
        p_hdec, W2, b2, out, TT * BB, VV, DD, DD, VV, 0);
}